// round 8
// baseline (speedup 1.0000x reference)
#include <cuda_runtime.h>
#include <cuda_bf16.h>
#include <stdint.h>

// Problem dims
#define E_  8
#define B_  4096
#define L_  512
#define H1_ 1024
#define H2_ 512
#define C_  40

// ---------------- scratch (device globals; allocation-free) ----------------
__device__ __align__(128) float         g_h1[B_ * H1_];            // fp32, selected
__device__ __align__(128) float         g_h2[B_ * H2_];            // fp32, selected
__device__ __align__(128) __nv_bfloat16 g_a1hi[B_ * 1024];
__device__ __align__(128) __nv_bfloat16 g_a1lo[B_ * 1024];
__device__ __align__(128) __nv_bfloat16 g_h1hi[B_ * H1_];
__device__ __align__(128) __nv_bfloat16 g_h1lo[B_ * H1_];
__device__ __align__(128) __nv_bfloat16 g_w1hiT[E_ * H1_ * 1024];  // [E][N][K]
__device__ __align__(128) __nv_bfloat16 g_w1loT[E_ * H1_ * 1024];
__device__ __align__(128) __nv_bfloat16 g_w2hiT[E_ * H2_ * H1_];
__device__ __align__(128) __nv_bfloat16 g_w2loT[E_ * H2_ * H1_];
__device__ int g_perm[B_];
__device__ int g_off[E_ + 1];
__device__ int g_cnt[E_];
__device__ int g_pos[E_];
__device__ int g_ok[4];                 // g_ok[1]: layer1 mma valid, g_ok[2]: layer2

// ---------------- tensor-core MMA ----------------
__device__ __forceinline__ void mma16816(float* c, const uint32_t* a, const uint32_t* b) {
    asm volatile("mma.sync.aligned.m16n8k16.row.col.f32.bf16.bf16.f32 "
        "{%0,%1,%2,%3}, {%4,%5,%6,%7}, {%8,%9}, {%0,%1,%2,%3};"
        : "+f"(c[0]), "+f"(c[1]), "+f"(c[2]), "+f"(c[3])
        : "r"(a[0]), "r"(a[1]), "r"(a[2]), "r"(a[3]), "r"(b[0]), "r"(b[1]));
}

// ---------------- counting sort (proven R1) ----------------
__global__ void k_init() {
    int t = threadIdx.x;
    if (t < E_) { g_cnt[t] = 0; g_pos[t] = 0; }
    if (t < 4)  g_ok[t] = 0;
}
__global__ void k_hist(const int* __restrict__ label) {
    int b = blockIdx.x * blockDim.x + threadIdx.x;
    if (b < B_) atomicAdd(&g_cnt[label[b]], 1);
}
__global__ void k_scan() {
    int s = 0; g_off[0] = 0;
    for (int e = 0; e < E_; e++) { s += g_cnt[e]; g_off[e + 1] = s; }
}
__global__ void k_scatter(const int* __restrict__ label) {
    int b = blockIdx.x * blockDim.x + threadIdx.x;
    if (b < B_) {
        int e = label[b];
        int p = atomicAdd(&g_pos[e], 1);
        g_perm[g_off[e] + p] = b;
    }
}

// ---------------- conversions (mma path inputs) ----------------
__global__ void __launch_bounds__(256)
k_xconv(const float* __restrict__ x_s, const float* __restrict__ x_p) {
    int idx = blockIdx.x * blockDim.x + threadIdx.x;   // B * 1024
    int s = idx >> 10, k = idx & 1023;
    int orig = g_perm[s];
    if ((unsigned)orig >= B_) orig = 0;
    float v = (k < L_) ? x_p[(size_t)orig * L_ + k] : x_s[(size_t)orig * L_ + (k - L_)];
    __nv_bfloat16 h = __float2bfloat16(v);
    __nv_bfloat16 l = __float2bfloat16(v - __bfloat162float(h));
    g_a1hi[idx] = h; g_a1lo[idx] = l;
}

template <int KDIM, int NDIM>
__global__ void __launch_bounds__(256)
k_wconv(const float* __restrict__ W,
        __nv_bfloat16* __restrict__ hiT, __nv_bfloat16* __restrict__ loT) {
    __shared__ float s[32][33];
    const int e = blockIdx.z;
    const int kt = blockIdx.y * 32, nt = blockIdx.x * 32;
    const float* Wp = W + (size_t)e * KDIM * NDIM;
    const int tx = threadIdx.x, ty = threadIdx.y;   // (32, 8)
#pragma unroll
    for (int i = 0; i < 32; i += 8)
        s[ty + i][tx] = Wp[(size_t)(kt + ty + i) * NDIM + nt + tx];
    __syncthreads();
#pragma unroll
    for (int i = 0; i < 32; i += 8) {
        int nn = ty + i;
        float v = s[tx][nn];
        __nv_bfloat16 h = __float2bfloat16(v);
        __nv_bfloat16 l = __float2bfloat16(v - __bfloat162float(h));
        size_t o = ((size_t)e * NDIM + nt + nn) * KDIM + kt + tx;
        hiT[o] = h; loT[o] = l;
    }
}

// selected fp32 h1 -> bf16 split (input for mma layer 2)
__global__ void __launch_bounds__(256)
k_aconv1() {
    int idx = blockIdx.x * blockDim.x + threadIdx.x;   // B * H1
    float v = g_h1[idx];
    __nv_bfloat16 h = __float2bfloat16(v);
    __nv_bfloat16 l = __float2bfloat16(v - __bfloat162float(h));
    g_h1hi[idx] = h; g_h1lo[idx] = l;
}

// ---------------- mma-path GEMM (suspect; output verified) ----------------
#define BMt 128
#define BNt 64
#define BKt 32
#define RS  40

template <int KDIM, int NOUT, int LAYER>
__global__ void __launch_bounds__(256)
k_mma(const float* __restrict__ bias) {
    __shared__ __align__(16) __nv_bfloat16 sAhi[BMt * RS];
    __shared__ __align__(16) __nv_bfloat16 sAlo[BMt * RS];
    __shared__ __align__(16) __nv_bfloat16 sBhi[BNt * RS];
    __shared__ __align__(16) __nv_bfloat16 sBlo[BNt * RS];

    const int e = blockIdx.z;
    int base = g_off[e], end = g_off[e + 1];
    base = max(0, min(base, B_));
    end  = max(base, min(end, B_));
    const int cnt = end - base;
    const int m0  = blockIdx.y * BMt;
    if (m0 >= cnt) return;
    const int n0 = blockIdx.x * BNt;

    const int t    = threadIdx.x;
    const int wid  = t >> 5, lane = t & 31;
    const int mw   = (wid & 3) * 32, nw = (wid >> 2) * 32;
    const int g    = lane >> 2, tg = lane & 3;

    const __nv_bfloat16* Ahi_g = (LAYER == 1) ? g_a1hi : g_h1hi;
    const __nv_bfloat16* Alo_g = (LAYER == 1) ? g_a1lo : g_h1lo;
    const __nv_bfloat16* Bhi_g = (LAYER == 1) ? g_w1hiT : g_w2hiT;
    const __nv_bfloat16* Blo_g = (LAYER == 1) ? g_w1loT : g_w2loT;

    const int as0 = t, as1 = t + 256;
    const int ar0 = as0 >> 2, ac0 = (as0 & 3) << 3;
    const int ar1 = as1 >> 2, ac1 = (as1 & 3) << 3;
    const size_t ga0 = (size_t)(base + m0 + ((m0 + ar0 < cnt) ? ar0 : 0));
    const size_t ga1 = (size_t)(base + m0 + ((m0 + ar1 < cnt) ? ar1 : 0));
    const int br = t >> 2, bc = (t & 3) << 3;
    const size_t gb = (size_t)e * NOUT + n0 + br;

    float acc[2][4][4];
#pragma unroll
    for (int i = 0; i < 2; i++)
#pragma unroll
        for (int j = 0; j < 4; j++)
#pragma unroll
            for (int k2 = 0; k2 < 4; k2++) acc[i][j][k2] = 0.f;

    uint4 pAh0, pAh1, pAl0, pAl1, pBh, pBl;
    auto fetch = [&](int kt) {
        pAh0 = *(const uint4*)(Ahi_g + ga0 * KDIM + kt + ac0);
        pAh1 = *(const uint4*)(Ahi_g + ga1 * KDIM + kt + ac1);
        pAl0 = *(const uint4*)(Alo_g + ga0 * KDIM + kt + ac0);
        pAl1 = *(const uint4*)(Alo_g + ga1 * KDIM + kt + ac1);
        pBh  = *(const uint4*)(Bhi_g + gb * KDIM + kt + bc);
        pBl  = *(const uint4*)(Blo_g + gb * KDIM + kt + bc);
    };

    const int nchunks = KDIM / BKt;
    fetch(0);
    for (int i = 0; i < nchunks; i++) {
        __syncthreads();
        *(uint4*)(sAhi + ar0 * RS + ac0) = pAh0;
        *(uint4*)(sAhi + ar1 * RS + ac1) = pAh1;
        *(uint4*)(sAlo + ar0 * RS + ac0) = pAl0;
        *(uint4*)(sAlo + ar1 * RS + ac1) = pAl1;
        *(uint4*)(sBhi + br * RS + bc)   = pBh;
        *(uint4*)(sBlo + br * RS + bc)   = pBl;
        __syncthreads();
        if (i + 1 < nchunks) fetch((i + 1) * BKt);

#pragma unroll
        for (int kk = 0; kk < BKt; kk += 16) {
            uint32_t ahi[2][4], alo[2][4], bhi[4][2], blo[4][2];
#pragma unroll
            for (int mi = 0; mi < 2; mi++) {
                int r = mw + mi * 16 + g;
                int kbase = kk + tg * 2;
                ahi[mi][0] = *(const uint32_t*)(sAhi + r * RS + kbase);
                ahi[mi][1] = *(const uint32_t*)(sAhi + (r + 8) * RS + kbase);
                ahi[mi][2] = *(const uint32_t*)(sAhi + r * RS + kbase + 8);
                ahi[mi][3] = *(const uint32_t*)(sAhi + (r + 8) * RS + kbase + 8);
                alo[mi][0] = *(const uint32_t*)(sAlo + r * RS + kbase);
                alo[mi][1] = *(const uint32_t*)(sAlo + (r + 8) * RS + kbase);
                alo[mi][2] = *(const uint32_t*)(sAlo + r * RS + kbase + 8);
                alo[mi][3] = *(const uint32_t*)(sAlo + (r + 8) * RS + kbase + 8);
            }
#pragma unroll
            for (int ni = 0; ni < 4; ni++) {
                int nr = nw + ni * 8 + g;
                int kbase = kk + tg * 2;
                bhi[ni][0] = *(const uint32_t*)(sBhi + nr * RS + kbase);
                bhi[ni][1] = *(const uint32_t*)(sBhi + nr * RS + kbase + 8);
                blo[ni][0] = *(const uint32_t*)(sBlo + nr * RS + kbase);
                blo[ni][1] = *(const uint32_t*)(sBlo + nr * RS + kbase + 8);
            }
#pragma unroll
            for (int mi = 0; mi < 2; mi++)
#pragma unroll
                for (int ni = 0; ni < 4; ni++) {
                    mma16816(acc[mi][ni], ahi[mi], bhi[ni]);
                    mma16816(acc[mi][ni], ahi[mi], blo[ni]);
                    mma16816(acc[mi][ni], alo[mi], bhi[ni]);
                }
        }
    }

    float* Out = (LAYER == 1) ? g_h1 : g_h2;
#pragma unroll
    for (int mi = 0; mi < 2; mi++) {
#pragma unroll
        for (int half = 0; half < 2; half++) {
            int row = m0 + mw + mi * 16 + g + half * 8;
            if (row >= cnt) continue;
#pragma unroll
            for (int ni = 0; ni < 4; ni++) {
                int n = n0 + nw + ni * 8 + tg * 2;
                float v0 = acc[mi][ni][half * 2 + 0] + bias[e * NOUT + n];
                float v1 = acc[mi][ni][half * 2 + 1] + bias[e * NOUT + n + 1];
                v0 = (v0 > 0.f) ? v0 : expm1f(v0);
                v1 = (v1 > 0.f) ? v1 : expm1f(v1);
                *reinterpret_cast<float2*>(&Out[(size_t)(base + row) * NOUT + n]) =
                    make_float2(v0, v1);
            }
        }
    }
}

// ---------------- checker: verify mma output on 2 rows x 64 cols ----------
template <int KDIM, int NOUT, int LAYER>
__global__ void __launch_bounds__(128)
k_check(const float* __restrict__ x_s, const float* __restrict__ x_p,
        const float* __restrict__ W, const float* __restrict__ bias) {
    const int t = threadIdx.x;
    if (t == 0) g_ok[LAYER] = 1;
    __syncthreads();

    const int srow = (t >> 6) ? (B_ - 1) : 0;
    int e = 0;
#pragma unroll
    for (int i = 0; i < E_ - 1; i++)
        if (g_off[i + 1] <= srow) e = i + 1;
    const int col = (t & 63) * (NOUT / 64);

    const float* Wc = W + (size_t)e * KDIM * NOUT + col;
    float acc = 0.f;
    if (LAYER == 1) {
        int orig = g_perm[srow];
        if ((unsigned)orig >= B_) orig = 0;
        const float* xpr = x_p + (size_t)orig * L_;
        const float* xsr = x_s + (size_t)orig * L_;
#pragma unroll 4
        for (int k = 0; k < KDIM; k++) {
            float a = (k < L_) ? xpr[k] : xsr[k - L_];
            acc += a * Wc[(size_t)k * NOUT];
        }
    } else {
        const float* ar = g_h1 + (size_t)srow * KDIM;
#pragma unroll 4
        for (int k = 0; k < KDIM; k++)
            acc += ar[k] * Wc[(size_t)k * NOUT];
    }
    acc += bias[e * NOUT + col];
    acc = (acc > 0.f) ? acc : expm1f(acc);

    const float got = ((LAYER == 1) ? g_h1 : g_h2)[(size_t)srow * NOUT + col];
    if (fabsf(got - acc) > 1e-2f * (1.f + fabsf(acc)))
        g_ok[LAYER] = 0;
}

// ---------------- fallback: proven R1 SIMT GEMM (gated on g_ok) ----------
#define BM 64
#define BN 64
#define BK 16

template <int KDIM, int NDIM, int LAYER>
__global__ void __launch_bounds__(256)
k_gemm(const float* __restrict__ x_s, const float* __restrict__ x_p,
       const float* __restrict__ W, const float* __restrict__ bias)
{
    if (g_ok[LAYER] != 0) return;   // mma output verified -> skip fallback

    const int e    = blockIdx.z;
    const int base = g_off[e];
    const int cnt  = g_off[e + 1] - base;
    const int m0   = blockIdx.y * BM;
    if (m0 >= cnt) return;
    const int n0 = blockIdx.x * BN;

    __shared__ float As[BK][BM];
    __shared__ float Bs[BK][BN];

    const int t = threadIdx.x;
    const int lm = t >> 2;
    const int lk = (t & 3) << 2;
    const int bk = t >> 4;
    const int bn = (t & 15) << 2;
    const int ty = t >> 4;
    const int tx = t & 15;

    const float* Wp = W + (size_t)e * KDIM * NDIM + n0;

    const float* arow0 = nullptr;
    const float* arow1 = nullptr;
    const bool avalid = (m0 + lm) < cnt;
    if (avalid) {
        if (LAYER == 1) {
            int r = g_perm[base + m0 + lm];
            arow0 = x_p + (size_t)r * L_;
            arow1 = x_s + (size_t)r * L_;
        } else {
            arow0 = g_h1 + (size_t)(base + m0 + lm) * KDIM;
        }
    }

    float acc[4][4];
#pragma unroll
    for (int i = 0; i < 4; i++)
#pragma unroll
        for (int j = 0; j < 4; j++) acc[i][j] = 0.f;

    for (int kt = 0; kt < KDIM; kt += BK) {
        float4 a4 = make_float4(0.f, 0.f, 0.f, 0.f);
        if (avalid) {
            int k = kt + lk;
            const float* p;
            if (LAYER == 1) p = (k < L_) ? (arow0 + k) : (arow1 + (k - L_));
            else            p = arow0 + k;
            a4 = *(const float4*)p;
        }
        As[lk + 0][lm] = a4.x;
        As[lk + 1][lm] = a4.y;
        As[lk + 2][lm] = a4.z;
        As[lk + 3][lm] = a4.w;

        *(float4*)&Bs[bk][bn] =
            *(const float4*)(Wp + (size_t)(kt + bk) * NDIM + bn);

        __syncthreads();

#pragma unroll
        for (int k = 0; k < BK; k++) {
            float4 a = *(const float4*)&As[k][ty << 2];
            float4 b = *(const float4*)&Bs[k][tx << 2];
            float av[4] = {a.x, a.y, a.z, a.w};
            float bv[4] = {b.x, b.y, b.z, b.w};
#pragma unroll
            for (int i = 0; i < 4; i++)
#pragma unroll
                for (int j = 0; j < 4; j++)
                    acc[i][j] += av[i] * bv[j];
        }
        __syncthreads();
    }

    float* Out = (LAYER == 1) ? g_h1 : g_h2;
#pragma unroll
    for (int i = 0; i < 4; i++) {
        int rm = m0 + (ty << 2) + i;
        if (rm >= cnt) break;
        size_t orow = (size_t)(base + rm) * NDIM;
#pragma unroll
        for (int j = 0; j < 4; j++) {
            int   n = n0 + (tx << 2) + j;
            float v = acc[i][j] + bias[e * NDIM + n];
            v = (v > 0.f) ? v : expm1f(v);
            Out[orow + n] = v;
        }
    }
}

// ---------------- layer 3: proven R1 SIMT ----------------
__global__ void __launch_bounds__(64)
k_l3(const float* __restrict__ W3, const float* __restrict__ b3,
     float* __restrict__ out) {
    const int srow = blockIdx.x;
    int e = 0;
#pragma unroll
    for (int i = 0; i < E_ - 1; i++)
        if (g_off[i + 1] <= srow) e = i + 1;
    const int orig = g_perm[srow];

    __shared__ float h[H2_];
    for (int k = threadIdx.x; k < H2_; k += blockDim.x)
        h[k] = g_h2[(size_t)srow * H2_ + k];
    __syncthreads();

    const int c = threadIdx.x;
    if (c < C_) {
        const float* W = W3 + (size_t)e * H2_ * C_;
        float acc = 0.f;
#pragma unroll 16
        for (int k = 0; k < H2_; k++)
            acc += h[k] * W[k * C_ + c];
        out[(size_t)orig * C_ + c] = acc + b3[e * C_ + c];
    }
}

// ---------------- launch ----------------
extern "C" void kernel_launch(void* const* d_in, const int* in_sizes, int n_in,
                              void* d_out, int out_size) {
    const float* x_s   = (const float*)d_in[0];
    const float* x_p   = (const float*)d_in[1];
    const float* W1    = (const float*)d_in[2];
    const float* b1    = (const float*)d_in[3];
    const float* W2    = (const float*)d_in[4];
    const float* b2    = (const float*)d_in[5];
    const float* W3    = (const float*)d_in[6];
    const float* b3    = (const float*)d_in[7];
    const int*   label = (const int*)d_in[8];
    (void)in_sizes; (void)n_in;
    float* out = (float*)d_out; (void)out_size;

    // sort (proven)
    k_init<<<1, 32>>>();
    k_hist<<<B_ / 256, 256>>>(label);
    k_scan<<<1, 1>>>();
    k_scatter<<<B_ / 256, 256>>>(label);

    // mma-path inputs
    k_wconv<1024, H1_><<<dim3(H1_ / 32, 1024 / 32, E_), dim3(32, 8)>>>(W1, g_w1hiT, g_w1loT);
    k_wconv<H1_, H2_><<<dim3(H2_ / 32, H1_ / 32, E_), dim3(32, 8)>>>(W2, g_w2hiT, g_w2loT);
    k_xconv<<<(B_ * 1024) / 256, 256>>>(x_s, x_p);

    // ---- layer 1: mma attempt -> verify -> fallback ----
    dim3 gm1(H1_ / BNt, B_ / BMt, E_);
    k_mma<1024, H1_, 1><<<gm1, 256>>>(b1);
    k_check<1024, H1_, 1><<<1, 128>>>(x_s, x_p, W1, b1);
    dim3 gf1(H1_ / BN, B_ / BM, E_);
    k_gemm<1024, H1_, 1><<<gf1, 256>>>(x_s, x_p, W1, b1);

    // split selected h1 for mma layer 2
    k_aconv1<<<(B_ * H1_) / 256, 256>>>();

    // ---- layer 2: mma attempt -> verify -> fallback ----
    dim3 gm2(H2_ / BNt, B_ / BMt, E_);
    k_mma<H1_, H2_, 2><<<gm2, 256>>>(b2);
    k_check<H1_, H2_, 2><<<1, 128>>>(x_s, x_p, W2, b2);
    dim3 gf2(H2_ / BN, B_ / BM, E_);
    k_gemm<H1_, H2_, 2><<<gf2, 256>>>(x_s, x_p, W2, b2);

    // ---- layer 3 (proven) ----
    k_l3<<<B_, 64>>>(W3, b3, out);
}